// round 9
// baseline (speedup 1.0000x reference)
#include <cuda_runtime.h>
#include <cuda_bf16.h>
#include <math.h>

typedef unsigned long long ull;

#define SS 2048
#define BB 64
#define II 512
#define HH 512
#define G3 1536   // 3*H
#define LL 2

// ---- Scratch (allocation-free rule: __device__ globals) --------------------
__device__ float g_xlin[(size_t)SS * G3 * BB];   // [S,3H,B]
__device__ float g_T1  [(size_t)SS * HH * BB];   // [S,H,B] layer-1 ys
__device__ __nv_bfloat16 g_bhi[(size_t)SS * BB * II];
__device__ __nv_bfloat16 g_blo[(size_t)SS * BB * II];
__device__ __nv_bfloat16 g_whi[(size_t)G3 * II];
__device__ __nv_bfloat16 g_wlo[(size_t)G3 * II];
// h exchange ring: [buf 4][bg 4][16 b][512 k] bf16 hi/lo
__device__ __nv_bfloat16 g_hb_hi[4 * 4 * 16 * 512];
__device__ __nv_bfloat16 g_hb_lo[4 * 4 * 16 * 512];
// per-batchgroup monotonic counters (each in own 128B line)
__device__ unsigned g_P[4 * 32];
__device__ unsigned g_C[4 * 32];

// ---------------------------------------------------------------------------
__global__ void split_bf16(const float* __restrict__ in,
                           __nv_bfloat16* __restrict__ hi,
                           __nv_bfloat16* __restrict__ lo, size_t n)
{
    size_t i = (size_t)blockIdx.x * blockDim.x + threadIdx.x;
    if (i < n) {
        float v = in[i];
        __nv_bfloat16 h = __float2bfloat16(v);
        hi[i] = h;
        lo[i] = __float2bfloat16(v - __bfloat162float(h));
    }
}

__global__ void reset_sync()
{
    if (threadIdx.x < 128) { g_P[threadIdx.x] = 0; g_C[threadIdx.x] = 0; }
}

// ---------------------------------------------------------------------------
__device__ __forceinline__ void mma_bf16(float* d, const unsigned* a, const unsigned* b)
{
    asm volatile(
        "mma.sync.aligned.m16n8k16.row.col.f32.bf16.bf16.f32 "
        "{%0,%1,%2,%3},{%4,%5,%6,%7},{%8,%9},{%0,%1,%2,%3};"
        : "+f"(d[0]), "+f"(d[1]), "+f"(d[2]), "+f"(d[3])
        : "r"(a[0]), "r"(a[1]), "r"(a[2]), "r"(a[3]), "r"(b[0]), "r"(b[1]));
}

__device__ __forceinline__ void ldmx4(unsigned* r, const __nv_bfloat16* p)
{
    unsigned addr = (unsigned)__cvta_generic_to_shared(p);
    asm volatile("ldmatrix.sync.aligned.m8n8.x4.shared.b16 {%0,%1,%2,%3}, [%4];"
                 : "=r"(r[0]), "=r"(r[1]), "=r"(r[2]), "=r"(r[3]) : "r"(addr));
}

__device__ __forceinline__ void cpasync16(void* dst, const void* src)
{
    unsigned d = (unsigned)__cvta_generic_to_shared(dst);
    asm volatile("cp.async.cg.shared.global [%0], [%1], 16;" :: "r"(d), "l"(src) : "memory");
}

__device__ __forceinline__ unsigned ld_acq(const unsigned* p)
{
    unsigned v;
    asm volatile("ld.acquire.gpu.global.u32 %0, [%1];" : "=r"(v) : "l"(p));
    return v;
}

__device__ __forceinline__ void red_rel(unsigned* p, unsigned v)
{
    asm volatile("red.release.gpu.global.add.u32 [%0], %1;" :: "l"(p), "r"(v) : "memory");
}

// ---------------------------------------------------------------------------
// xlinT[s, n, b] = sum_k W[n,k] * X[s,b,k] + bias[n]  (bf16x3 mma)
// ---------------------------------------------------------------------------
#define BMN 128
#define BNB 64
#define BK  32
#define LDT 40

template <int BT>
__global__ __launch_bounds__(256, 2) void gemm_xlinT(
    const __nv_bfloat16* __restrict__ Whi, const __nv_bfloat16* __restrict__ Wlo,
    const __nv_bfloat16* __restrict__ Xhi, const __nv_bfloat16* __restrict__ Xlo,
    const float* __restrict__ bias, float* __restrict__ C)
{
    __shared__ __align__(16) __nv_bfloat16 sA[2][BMN * LDT];
    __shared__ __align__(16) __nv_bfloat16 sB[2][BNB * LDT];

    int tid  = threadIdx.x;
    int s    = blockIdx.x;
    int n0   = blockIdx.y * BMN;
    int w    = tid >> 5, lane = tid & 31;
    int wm   = w >> 1,   wn   = w & 1;

    const __nv_bfloat16* Xh = Xhi + (size_t)s * BB * II;
    const __nv_bfloat16* Xl = Xlo + (size_t)s * BB * II;

    float acc[2][4][4];
#pragma unroll
    for (int i = 0; i < 2; i++)
#pragma unroll
        for (int j = 0; j < 4; j++)
#pragma unroll
            for (int k = 0; k < 4; k++) acc[i][j][k] = 0.f;

    for (int k0 = 0; k0 < II; k0 += BK) {
        __syncthreads();
#pragma unroll
        for (int v = 0; v < 2; v++) {
            int fi = tid + v * 256;
            int r  = fi >> 2, kq = fi & 3;
            const uint4* gh = reinterpret_cast<const uint4*>(Whi + (size_t)(n0 + r) * II + k0);
            const uint4* gl = reinterpret_cast<const uint4*>(Wlo + (size_t)(n0 + r) * II + k0);
            reinterpret_cast<uint4*>(&sA[0][(size_t)r * LDT])[kq] = gh[kq];
            reinterpret_cast<uint4*>(&sA[1][(size_t)r * LDT])[kq] = gl[kq];
        }
        if (BT == 0) {
            int r = tid >> 2, kq = tid & 3;
            const uint4* gh = reinterpret_cast<const uint4*>(Xh + (size_t)r * II + k0);
            const uint4* gl = reinterpret_cast<const uint4*>(Xl + (size_t)r * II + k0);
            reinterpret_cast<uint4*>(&sB[0][(size_t)r * LDT])[kq] = gh[kq];
            reinterpret_cast<uint4*>(&sB[1][(size_t)r * LDT])[kq] = gl[kq];
        } else {
            int kk = tid >> 3;
            int bo = (tid & 7) * 8;
            uint4 vh = *reinterpret_cast<const uint4*>(Xh + (size_t)(k0 + kk) * BB + bo);
            uint4 vl = *reinterpret_cast<const uint4*>(Xl + (size_t)(k0 + kk) * BB + bo);
            const unsigned short* ph = reinterpret_cast<const unsigned short*>(&vh);
            const unsigned short* pl = reinterpret_cast<const unsigned short*>(&vl);
            unsigned short* s0 = reinterpret_cast<unsigned short*>(sB[0]);
            unsigned short* s1 = reinterpret_cast<unsigned short*>(sB[1]);
#pragma unroll
            for (int e = 0; e < 8; e++) {
                s0[(size_t)(bo + e) * LDT + kk] = ph[e];
                s1[(size_t)(bo + e) * LDT + kk] = pl[e];
            }
        }
        __syncthreads();

#pragma unroll
        for (int kh = 0; kh < 2; kh++) {
            int koff = kh * 16;
            unsigned af[2][2][4];
            unsigned bf[4][2][2];
            int q = lane >> 3, lr = lane & 7;
#pragma unroll
            for (int mt = 0; mt < 2; mt++) {
                const __nv_bfloat16* pa =
                    &sA[0][(size_t)(wm * 32 + mt * 16 + (q & 1) * 8 + lr) * LDT + koff + (q >> 1) * 8];
                ldmx4(af[mt][0], pa);
                ldmx4(af[mt][1], pa + BMN * LDT);
            }
#pragma unroll
            for (int j = 0; j < 2; j++) {
                int ntile = 2 * j + (q >> 1);
                const __nv_bfloat16* pb =
                    &sB[0][(size_t)(wn * 32 + ntile * 8 + lr) * LDT + koff + (q & 1) * 8];
                unsigned t[4];
                ldmx4(t, pb);
                bf[2 * j][0][0] = t[0]; bf[2 * j][0][1] = t[1];
                bf[2 * j + 1][0][0] = t[2]; bf[2 * j + 1][0][1] = t[3];
                ldmx4(t, pb + BNB * LDT);
                bf[2 * j][1][0] = t[0]; bf[2 * j][1][1] = t[1];
                bf[2 * j + 1][1][0] = t[2]; bf[2 * j + 1][1][1] = t[3];
            }
#pragma unroll
            for (int mt = 0; mt < 2; mt++)
#pragma unroll
                for (int nt = 0; nt < 4; nt++) {
                    mma_bf16(acc[mt][nt], af[mt][0], bf[nt][0]);
                    mma_bf16(acc[mt][nt], af[mt][0], bf[nt][1]);
                    mma_bf16(acc[mt][nt], af[mt][1], bf[nt][0]);
                }
        }
    }

#pragma unroll
    for (int mt = 0; mt < 2; mt++)
#pragma unroll
        for (int nt = 0; nt < 4; nt++) {
            int row  = n0 + wm * 32 + mt * 16 + (lane >> 2);
            int colb = wn * 32 + nt * 8 + (lane & 3) * 2;
            float bias0 = bias[row], bias1 = bias[row + 8];
            float2 o0 = {acc[mt][nt][0] + bias0, acc[mt][nt][1] + bias0};
            float2 o1 = {acc[mt][nt][2] + bias1, acc[mt][nt][3] + bias1};
            *reinterpret_cast<float2*>(C + ((size_t)s * G3 + row) * BB + colb) = o0;
            *reinterpret_cast<float2*>(C + ((size_t)s * G3 + row + 8) * BB + colb) = o1;
        }
}

// ---------------------------------------------------------------------------
// Persistent scan, mma-based. 128 CTAs = 32 colgroups x 4 batchgroups.
// CTA: 16 cols x 16 batches. Warp w owns K-slice [w*64, w*64+64) (loads its
// own h slice via cp.async, warp-local sync only). 4-deep h ring in gmem,
// acquire/release flag sync, coalesced producer stores via smem staging.
// ---------------------------------------------------------------------------
#define LDW 520
#define LDH 520
#define OFF_WHI 0
#define OFF_WLO (48 * LDW * 2)
#define OFF_HHI (2 * 48 * LDW * 2)
#define OFF_HLO (OFF_HHI + 16 * LDH * 2)
#define OFF_RED (OFF_HLO + 16 * LDH * 2)
#define OFF_STG (OFF_RED + 8 * 768 * 4)
#define SCAN_SMEM (OFF_STG + 2 * 16 * 16 * 2)

__device__ __forceinline__ float sigmoidf_(float x) { return 1.0f / (1.0f + expf(-x)); }

__global__ __launch_bounds__(256, 1) void scan_layer(
    const float* __restrict__ xlT,    // [S, 3H, B]
    const float* __restrict__ whh_l,  // [3H, H]
    const float* __restrict__ bhh_l,  // [3H]
    const float* __restrict__ h0,     // [B, H]
    float* __restrict__ ysT,          // [S, H, B]
    float* __restrict__ hfin)         // [B, H]
{
    extern __shared__ char sm[];
    __nv_bfloat16* sWhi = reinterpret_cast<__nv_bfloat16*>(sm + OFF_WHI);
    __nv_bfloat16* sWlo = reinterpret_cast<__nv_bfloat16*>(sm + OFF_WLO);
    __nv_bfloat16* sHhi = reinterpret_cast<__nv_bfloat16*>(sm + OFF_HHI);
    __nv_bfloat16* sHlo = reinterpret_cast<__nv_bfloat16*>(sm + OFF_HLO);
    float*         red  = reinterpret_cast<float*>(sm + OFF_RED);
    __nv_bfloat16* stg  = reinterpret_cast<__nv_bfloat16*>(sm + OFF_STG);  // [2][16][16]

    int tid  = threadIdx.x;
    int lane = tid & 31;
    int w    = tid >> 5;
    int cg   = blockIdx.x >> 2;
    int bg   = blockIdx.x & 3;
    int q    = lane >> 3, lr = lane & 7;

    // ---- convert weight slice to bf16 hi/lo (once) ----
    for (int i = tid; i < 48 * 512; i += 256) {
        int m = i >> 9, k = i & 511;
        int g = m >> 4, c = m & 15;
        float v = whh_l[((size_t)(g * 512 + cg * 16 + c)) * 512 + k];
        __nv_bfloat16 hi = __float2bfloat16(v);
        sWhi[m * LDW + k] = hi;
        sWlo[m * LDW + k] = __float2bfloat16(v - __bfloat162float(hi));
    }
    __syncthreads();

    // ---- preload A fragments for the whole scan ----
    unsigned afh[3][4][4], afl[3][4][4];
#pragma unroll
    for (int mt = 0; mt < 3; mt++)
#pragma unroll
        for (int kt = 0; kt < 4; kt++) {
            int idx = (mt * 16 + (q & 1) * 8 + lr) * LDW + (w * 4 + kt) * 16 + (q >> 1) * 8;
            ldmx4(afh[mt][kt], sWhi + idx);
            ldmx4(afl[mt][kt], sWlo + idx);
        }

    int c_own  = tid >> 4;
    int bl_own = tid & 15;
    int col    = cg * 16 + c_own;
    int bglob  = bg * 16 + bl_own;
    float hp = h0[(size_t)bglob * 512 + col];
    float bR = bhh_l[col], bZ = bhh_l[512 + col], bN = bhh_l[1024 + col];

    unsigned* Pf = g_P + bg * 32;
    unsigned* Cf = g_C + bg * 32;

    // warp-slice load mapping: lane -> (b, chunk-half)
    int lb   = lane & 15;        // batch row
    int lrem = lane >> 4;        // 0/1

    for (int s = 0; s < SS; s++) {
        // gate inputs: issue before poll (overlaps the wait)
        const float* xp = xlT + ((size_t)s * G3 + col) * 64 + bglob;
        float xr = __ldg(xp);
        float xz = __ldg(xp + 512 * 64);
        float xn = __ldg(xp + 1024 * 64);

        // ---- consumer: wait for h_{s-1}, load own warp slice ----
        if (s > 0) {
            if (lane == 0) {
                unsigned tgt = 32u * (unsigned)s;
                while (ld_acq(Pf) < tgt) { }
            }
            __syncwarp();
            size_t base = (size_t)((((s - 1) & 3) * 4 + bg) * 16 + lb) * 512;
#pragma unroll
            for (int j = 0; j < 4; j++) {
                int kc = lrem + j * 2;                 // 0..7
                int ko = w * 64 + kc * 8;
                cpasync16(sHhi + lb * LDH + ko, g_hb_hi + base + ko);
                cpasync16(sHlo + lb * LDH + ko, g_hb_lo + base + ko);
            }
            asm volatile("cp.async.commit_group;" ::: "memory");
            asm volatile("cp.async.wait_group 0;" ::: "memory");
            __syncwarp();
        } else {
            // convert h0 slice (warp-private region)
            for (int i = lane; i < 16 * 64; i += 32) {
                int b = i >> 6, k = w * 64 + (i & 63);
                float v = h0[(size_t)(bg * 16 + b) * 512 + k];
                __nv_bfloat16 hi = __float2bfloat16(v);
                sHhi[b * LDH + k] = hi;
                sHlo[b * LDH + k] = __float2bfloat16(v - __bfloat162float(hi));
            }
            __syncwarp();
        }

        // ---- mma over own K-slice ----
        float acc[3][2][4];
#pragma unroll
        for (int i = 0; i < 3; i++)
#pragma unroll
            for (int j = 0; j < 2; j++)
#pragma unroll
                for (int k = 0; k < 4; k++) acc[i][j][k] = 0.f;

#pragma unroll
        for (int kt = 0; kt < 4; kt++) {
            unsigned bh[4], bl4[4];
            int hidx = ((q >> 1) * 8 + lr) * LDH + (w * 4 + kt) * 16 + (q & 1) * 8;
            ldmx4(bh, sHhi + hidx);
            ldmx4(bl4, sHlo + hidx);
#pragma unroll
            for (int mt = 0; mt < 3; mt++) {
                mma_bf16(acc[mt][0], afh[mt][kt], bh);
                mma_bf16(acc[mt][0], afh[mt][kt], bl4);
                mma_bf16(acc[mt][0], afl[mt][kt], bh);
                mma_bf16(acc[mt][1], afh[mt][kt], bh + 2);
                mma_bf16(acc[mt][1], afh[mt][kt], bl4 + 2);
                mma_bf16(acc[mt][1], afl[mt][kt], bh + 2);
            }
        }

        // ---- stash partials ----
#pragma unroll
        for (int mt = 0; mt < 3; mt++)
#pragma unroll
            for (int nt = 0; nt < 2; nt++) {
                int m = mt * 16 + (lane >> 2);
                int n = nt * 8 + (lane & 3) * 2;
                *reinterpret_cast<float2*>(&red[w * 768 + m * 16 + n]) =
                    make_float2(acc[mt][nt][0], acc[mt][nt][1]);
                *reinterpret_cast<float2*>(&red[w * 768 + (m + 8) * 16 + n]) =
                    make_float2(acc[mt][nt][2], acc[mt][nt][3]);
            }
        __syncthreads();   // bar1: all loads+mma+red writes done

        if (tid == 0) red_rel(Cf, 1u);   // CTA finished reading hb[s-1]

        // ---- reduce + gates (1 output per thread) ----
        float v0 = 0.f, v1 = 0.f, v2 = 0.f;
#pragma unroll
        for (int ww = 0; ww < 8; ww++) {
            v0 += red[ww * 768 + tid];
            v1 += red[ww * 768 + 256 + tid];
            v2 += red[ww * 768 + 512 + tid];
        }

        float r  = sigmoidf_(xr + v0 + bR);
        float z  = sigmoidf_(xz + v1 + bZ);
        float nn = tanhf(xn + r * (v2 + bN));
        float hn = (1.f - z) * nn + z * hp;
        hp = hn;

        ysT[((size_t)s * 512 + col) * 64 + bglob] = hn;
        if (s == SS - 1) hfin[(size_t)bglob * 512 + col] = hn;

        // stage hi/lo for coalesced store
        __nv_bfloat16 hb = __float2bfloat16(hn);
        stg[bl_own * 16 + c_own]       = hb;
        stg[256 + bl_own * 16 + c_own] = __float2bfloat16(hn - __bfloat162float(hb));

        // producer ring-slot guard: consumers must be done with slot s&3
        // (read at step s-3) -> C >= 32*(s-2). 3 steps of slack: rarely blocks.
        int tc = 32 * (s - 2);
        if (tc > 0 && lane == 0) {
            while ((int)ld_acq(Cf) < tc) { }
        }
        __syncthreads();   // bar2: stage complete + C-guard passed

        // ---- crew store (warp 0): 2x512B contiguous + release flag ----
        if (w == 0) {
            int b    = lane >> 1;
            int half = lane & 1;
            size_t go = (size_t)(((s & 3) * 4 + bg) * 16 + b) * 512 + cg * 16 + half * 8;
            *reinterpret_cast<uint4*>(g_hb_hi + go) =
                *reinterpret_cast<const uint4*>(stg + b * 16 + half * 8);
            *reinterpret_cast<uint4*>(g_hb_lo + go) =
                *reinterpret_cast<const uint4*>(stg + 256 + b * 16 + half * 8);
            __syncwarp();
            if (lane == 0) red_rel(Pf, 1u);
        }
    }
}

// ---------------------------------------------------------------------------
// [S,H,B] -> [S,B,H]
// ---------------------------------------------------------------------------
__global__ __launch_bounds__(256) void transpose_out(
    const float* __restrict__ in, float* __restrict__ out)
{
    __shared__ float t[32][33];
    int s  = blockIdx.z;
    int h0 = blockIdx.x * 32;
    int b0 = blockIdx.y * 32;
    int tx = threadIdx.x, ty = threadIdx.y;

#pragma unroll
    for (int r = 0; r < 4; r++)
        t[ty + r * 8][tx] = in[((size_t)s * HH + h0 + ty + r * 8) * BB + b0 + tx];
    __syncthreads();
#pragma unroll
    for (int r = 0; r < 4; r++)
        out[((size_t)s * BB + b0 + ty + r * 8) * HH + h0 + tx] = t[tx][ty + r * 8];
}

// ---------------------------------------------------------------------------
extern "C" void kernel_launch(void* const* d_in, const int* in_sizes, int n_in,
                              void* d_out, int out_size)
{
    const float* x   = (const float*)d_in[0];
    const float* hx  = (const float*)d_in[1];
    const float* wih = (const float*)d_in[2];
    const float* whh = (const float*)d_in[3];
    const float* bih = (const float*)d_in[4];
    const float* bhh = (const float*)d_in[5];

    float* out    = (float*)d_out;
    float* hidden = out + (size_t)SS * BB * HH;

    float *p_xlin, *p_T1;
    __nv_bfloat16 *p_bhi, *p_blo, *p_whi, *p_wlo;
    cudaGetSymbolAddress((void**)&p_xlin, g_xlin);
    cudaGetSymbolAddress((void**)&p_T1,   g_T1);
    cudaGetSymbolAddress((void**)&p_bhi,  g_bhi);
    cudaGetSymbolAddress((void**)&p_blo,  g_blo);
    cudaGetSymbolAddress((void**)&p_whi,  g_whi);
    cudaGetSymbolAddress((void**)&p_wlo,  g_wlo);

    static int attr_done = 0;
    if (!attr_done) {
        cudaFuncSetAttribute(scan_layer,
                             cudaFuncAttributeMaxDynamicSharedMemorySize, SCAN_SMEM);
        attr_done = 1;
    }

    const size_t nX = (size_t)SS * BB * II;
    const size_t nW = (size_t)G3 * II;
    dim3 ggrid(SS, G3 / BMN);
    dim3 tgrid(HH / 32, BB / 32, SS);
    dim3 tblk(32, 8);

    for (int l = 0; l < LL; l++) {
        const float* Bsrc = (l == 0) ? x : p_T1;

        split_bf16<<<(unsigned)((nW + 255) / 256), 256>>>(wih + (size_t)l * nW, p_whi, p_wlo, nW);
        split_bf16<<<(unsigned)((nX + 255) / 256), 256>>>(Bsrc, p_bhi, p_blo, nX);

        if (l == 0)
            gemm_xlinT<0><<<ggrid, 256>>>(p_whi, p_wlo, p_bhi, p_blo,
                                          bih + (size_t)l * G3, p_xlin);
        else
            gemm_xlinT<1><<<ggrid, 256>>>(p_whi, p_wlo, p_bhi, p_blo,
                                          bih + (size_t)l * G3, p_xlin);

        reset_sync<<<1, 128>>>();

        scan_layer<<<128, 256, SCAN_SMEM>>>(
            p_xlin,
            whh + (size_t)l * G3 * HH,
            bhh + (size_t)l * G3,
            hx  + (size_t)l * BB * HH,
            p_T1,
            hidden + (size_t)l * BB * HH);
    }

    transpose_out<<<tgrid, tblk>>>(p_T1, out);
}